// round 1
// baseline (speedup 1.0000x reference)
#include <cuda_runtime.h>
#include <math.h>

#define D      128
#define BMAX   1024
#define CHUNK  512

// Scratch (allocation-free rule: __device__ globals)
__device__ float g_sum[BMAX * D];
__device__ int   g_cnt[BMAX];

// softplus with the reference's Threshold(-50, 50) folding:
// ps = sp if sp < 50 else -50
__device__ __forceinline__ float softplus_thresh(float v) {
    float sp = fmaxf(v, 0.0f) + log1pf(expf(-fabsf(v)));
    return sp < 50.0f ? sp : -50.0f;
}

// ---------------------------------------------------------------------------
// Kernel 1: per-segment sum of (|x|+eps)^p  (p = ps0 for d<64, ps1 for d>=64)
// plus per-segment node counts. batch is sorted -> register runs + atomic flush.
// Thread layout: 128 threads = 32 feature-quads (tx) x 4 node lanes (ty).
// ---------------------------------------------------------------------------
__global__ void __launch_bounds__(128)
k1_pool(const float* __restrict__ x, const void* __restrict__ batch,
        const float* __restrict__ ps_raw, int N)
{
    __shared__ int sseg[CHUNK];

    const int tid = threadIdx.x;
    const int tx  = tid & 31;   // feature quad index: features [4*tx, 4*tx+3]
    const int ty  = tid >> 5;   // node lane 0..3 (== warp id)

    const long long start = (long long)blockIdx.x * CHUNK;
    const int len = (int)min((long long)CHUNK, (long long)N - start);

    // --- detect int32 vs int64 batch dtype (uniform across grid) ---
    // u64 read at ~N/4 (16B-aligned index): int64 buffer -> value < 1024;
    // int32 buffer -> (seg[~N/2] | seg[~N/2+1]<<32) >= 2^32.
    const unsigned long long* p64b = (const unsigned long long*)batch;
    size_t q = ((size_t)(N >> 2)) & ~(size_t)1;
    const bool is64 = (p64b[q] < (1ull << 20));

    if (is64) {
        const long long* bb = (const long long*)batch;
        for (int i = tid; i < len; i += 128) sseg[i] = (int)bb[start + i];
    } else {
        const int* bb = (const int*)batch;
        for (int i = tid; i < len; i += 128) sseg[i] = bb[start + i];
    }
    __syncthreads();

    const float p = softplus_thresh(ps_raw[tx < 16 ? 0 : 1]);

    const float4* __restrict__ x4 = (const float4*)x;
    const int fb = tx * 4;

    float ax = 0.f, ay = 0.f, az = 0.f, aw = 0.f;
    int cur = -1;
    int cnt = 0;

    for (int i = ty; i < len; i += 4) {
        int b = sseg[i];
        if (b != cur) {
            if (cnt > 0) {
                float* s = &g_sum[cur * D + fb];
                atomicAdd(s + 0, ax); atomicAdd(s + 1, ay);
                atomicAdd(s + 2, az); atomicAdd(s + 3, aw);
                if (tx == 0) atomicAdd(&g_cnt[cur], cnt);
                ax = ay = az = aw = 0.f;
                cnt = 0;
            }
            cur = b;
        }
        float4 v = x4[(size_t)(start + i) * 32 + tx];
        ax += __powf(fabsf(v.x) + 1e-6f, p);
        ay += __powf(fabsf(v.y) + 1e-6f, p);
        az += __powf(fabsf(v.z) + 1e-6f, p);
        aw += __powf(fabsf(v.w) + 1e-6f, p);
        cnt++;
    }
    if (cnt > 0) {
        float* s = &g_sum[cur * D + fb];
        atomicAdd(s + 0, ax); atomicAdd(s + 1, ay);
        atomicAdd(s + 2, az); atomicAdd(s + 3, aw);
        if (tx == 0) atomicAdd(&g_cnt[cur], cnt);
    }
}

// ---------------------------------------------------------------------------
// Kernel 2: gnp[b][d] = s[b][d]^(1/p_d) * n_b^(-qs0);  out = gnp @ W^T + bias
// One block handles 4 graph rows. W staged in smem with stride-65 padding
// (conflict-free), split into two K=64 halves to stay under 48KB static smem.
// ---------------------------------------------------------------------------
__global__ void __launch_bounds__(128)
k2_gemm(const float* __restrict__ W, const float* __restrict__ bias,
        const float* __restrict__ ps_raw, const float* __restrict__ qs_raw,
        float* __restrict__ out)
{
    __shared__ float gs[4][D];
    __shared__ float w[128 * 65];

    const int o  = threadIdx.x;       // output / feature index
    const int b0 = blockIdx.x * 4;

    const float qs0  = tanhf(qs_raw[0]);
    const float p    = softplus_thresh(ps_raw[o < 64 ? 0 : 1]);
    const float invp = 1.0f / p;

    // gnp for 4 rows (thread o computes feature d = o)
    #pragma unroll
    for (int r = 0; r < 4; r++) {
        int b = b0 + r;
        float s = g_sum[b * D + o];
        float n = (float)g_cnt[b];
        gs[r][o] = __powf(s, invp) * __powf(n, -qs0);
    }
    __syncthreads();

    float acc0 = bias[o], acc1 = acc0, acc2 = acc0, acc3 = acc0;

    #pragma unroll
    for (int half = 0; half < 2; half++) {
        // stage W[:, half*64 .. half*64+63] into w[o2*65 + dk]
        for (int idx = o; idx < 128 * 64; idx += 128) {
            int o2 = idx >> 6, dk = idx & 63;
            w[o2 * 65 + dk] = W[o2 * 128 + half * 64 + dk];
        }
        __syncthreads();

        #pragma unroll
        for (int dk = 0; dk < 64; dk++) {
            float wv = w[o * 65 + dk];     // bank = (o+dk)%32 -> conflict-free
            int d = half * 64 + dk;
            acc0 += gs[0][d] * wv;         // gs reads broadcast
            acc1 += gs[1][d] * wv;
            acc2 += gs[2][d] * wv;
            acc3 += gs[3][d] * wv;
        }
        __syncthreads();
    }

    out[(size_t)(b0 + 0) * D + o] = acc0;
    out[(size_t)(b0 + 1) * D + o] = acc1;
    out[(size_t)(b0 + 2) * D + o] = acc2;
    out[(size_t)(b0 + 3) * D + o] = acc3;
}

// ---------------------------------------------------------------------------
extern "C" void kernel_launch(void* const* d_in, const int* in_sizes, int n_in,
                              void* d_out, int out_size)
{
    const float* x      = (const float*)d_in[0];
    const void*  batch  = d_in[1];
    const float* ps_raw = (const float*)d_in[2];
    const float* qs_raw = (const float*)d_in[3];
    const float* W      = (const float*)d_in[4];
    const float* bias   = (const float*)d_in[5];
    float*       out    = (float*)d_out;

    const int N = in_sizes[1];        // node count (batch element count)
    const int B = out_size / D;       // 1024

    void *sum_ptr = nullptr, *cnt_ptr = nullptr;
    cudaGetSymbolAddress(&sum_ptr, g_sum);
    cudaGetSymbolAddress(&cnt_ptr, g_cnt);
    cudaMemsetAsync(sum_ptr, 0, (size_t)B * D * sizeof(float));
    cudaMemsetAsync(cnt_ptr, 0, (size_t)B * sizeof(int));

    const int grid1 = (N + CHUNK - 1) / CHUNK;
    k1_pool<<<grid1, 128>>>(x, batch, ps_raw, N);
    k2_gemm<<<B / 4, 128>>>(W, bias, ps_raw, qs_raw, out);
}

// round 2
// speedup vs baseline: 1.1940x; 1.1940x over previous
#include <cuda_runtime.h>
#include <math.h>

#define D      128
#define BMAX   1024
#define CHUNK  1024

// Scratch (allocation-free rule: __device__ globals)
__device__ float g_sum[BMAX * D];
__device__ int   g_cnt[BMAX];

// softplus with the reference's Threshold(-50, 50) folding
__device__ __forceinline__ float softplus_thresh(float v) {
    float sp = fmaxf(v, 0.0f) + log1pf(expf(-fabsf(v)));
    return sp < 50.0f ? sp : -50.0f;
}

// ---------------------------------------------------------------------------
// Kernel 1: per-segment sum of (|x|+eps)^p  (p = ps0 for d<64, ps1 for d>=64)
// plus per-segment node counts. batch is sorted -> register runs + atomic
// flush on boundary. 256 threads = 32 feature-quads (tx) x 8 node lanes (ty).
// Software-pipelined: next node's LDG + seg issued before current pow chain.
// ---------------------------------------------------------------------------
__global__ void __launch_bounds__(256)
k1_pool(const float* __restrict__ x, const void* __restrict__ batch,
        const float* __restrict__ ps_raw, int N)
{
    __shared__ int sseg[CHUNK];

    const int tid = threadIdx.x;
    const int tx  = tid & 31;   // feature quad: features [4*tx, 4*tx+3]
    const int ty  = tid >> 5;   // node lane 0..7

    const long long start = (long long)blockIdx.x * CHUNK;
    const int len = (int)min((long long)CHUNK, (long long)N - start);

    // detect int32 vs int64 batch dtype (uniform across grid):
    // u64 read at even idx ~N/4: int64 buffer -> small value; int32 -> >= 2^32
    const unsigned long long* p64b = (const unsigned long long*)batch;
    size_t q = ((size_t)(N >> 2)) & ~(size_t)1;
    const bool is64 = (p64b[q] < (1ull << 20));

    if (is64) {
        const long long* bb = (const long long*)batch;
        for (int i = tid; i < len; i += 256) sseg[i] = (int)bb[start + i];
    } else {
        const int* bb = (const int*)batch;
        for (int i = tid; i < len; i += 256) sseg[i] = bb[start + i];
    }
    __syncthreads();

    const float p = softplus_thresh(ps_raw[tx >> 4]);

    const float4* __restrict__ x4 = (const float4*)x;

    float ax = 0.f, ay = 0.f, az = 0.f, aw = 0.f;
    int cur = -1;
    int cnt = 0;

    int i = ty;
    if (i < len) {
        float4 v = x4[(size_t)(start + i) * 32 + tx];
        int b = sseg[i];
        while (true) {
            // prefetch next iteration before the dependent pow chain (MLP=2)
            int nx = i + 8;
            bool has = nx < len;
            float4 vn; int bn = -1;
            if (has) {
                vn = x4[(size_t)(start + nx) * 32 + tx];
                bn = sseg[nx];
            }
            if (b != cur) {
                if (cnt > 0) {
                    float* s = &g_sum[cur * D + tx * 4];
                    atomicAdd(s + 0, ax); atomicAdd(s + 1, ay);
                    atomicAdd(s + 2, az); atomicAdd(s + 3, aw);
                    if (tx == 0) atomicAdd(&g_cnt[cur], cnt);
                    ax = ay = az = aw = 0.f;
                    cnt = 0;
                }
                cur = b;
            }
            ax += __powf(fabsf(v.x) + 1e-6f, p);
            ay += __powf(fabsf(v.y) + 1e-6f, p);
            az += __powf(fabsf(v.z) + 1e-6f, p);
            aw += __powf(fabsf(v.w) + 1e-6f, p);
            cnt++;
            if (!has) break;
            v = vn; b = bn; i = nx;
        }
        if (cnt > 0) {
            float* s = &g_sum[cur * D + tx * 4];
            atomicAdd(s + 0, ax); atomicAdd(s + 1, ay);
            atomicAdd(s + 2, az); atomicAdd(s + 3, aw);
            if (tx == 0) atomicAdd(&g_cnt[cur], cnt);
        }
    }
}

// ---------------------------------------------------------------------------
// Kernel 2: gnp[b][d] = s[b][d]^(1/p_d) * n_b^(-qs0);  out = gnp @ W^T + bias
// 256 threads: o = tid&127 (output col), g = tid>>7 selects 2 of 4 graph rows.
// W staged per-64-K-half in smem with float4, stride 68 (17 float4) padding
// -> conflict-free LDS.128 in quarter-warp phases.
// ---------------------------------------------------------------------------
__global__ void __launch_bounds__(256)
k2_gemm(const float* __restrict__ W, const float* __restrict__ bias,
        const float* __restrict__ ps_raw, const float* __restrict__ qs_raw,
        float* __restrict__ out)
{
    __shared__ float w[128 * 68];     // 34.8 KB
    __shared__ float gs[4 * 128];     // 2 KB

    const int tid = threadIdx.x;
    const int o   = tid & 127;
    const int g   = tid >> 7;         // 0 or 1 -> rows {0,1} / {2,3}
    const int b0  = blockIdx.x * 4;

    const float qs0 = tanhf(qs_raw[0]);

    // gnp for 4 rows: 512 entries, 2 per thread
    for (int idx = tid; idx < 512; idx += 256) {
        int r = idx >> 7, d = idx & 127;
        float p = softplus_thresh(ps_raw[d >> 6]);
        float s = g_sum[(b0 + r) * D + d];
        float n = (float)g_cnt[b0 + r];
        gs[idx] = __powf(s, 1.0f / p) * __powf(n, -qs0);
    }

    float acc0 = bias[o], acc1 = acc0;    // rows g*2 and g*2+1

    const float4* __restrict__ W4 = (const float4*)W;
    float4* w4 = (float4*)w;
    const float4* gs4 = (const float4*)gs;

    #pragma unroll
    for (int half = 0; half < 2; half++) {
        __syncthreads();   // also covers gs writes before first read
        // stage W[:, half*64 .. half*64+63]: 128 rows x 16 float4
        for (int idx = tid; idx < 128 * 16; idx += 256) {
            int o2 = idx >> 4, dk4 = idx & 15;
            w4[o2 * 17 + dk4] = W4[o2 * 32 + half * 16 + dk4];
        }
        __syncthreads();

        #pragma unroll
        for (int dk4 = 0; dk4 < 16; dk4++) {
            float4 wv = w4[o * 17 + dk4];
            int d4 = half * 16 + dk4;
            float4 g0 = gs4[(g * 2)     * 32 + d4];   // broadcast LDS
            float4 g1 = gs4[(g * 2 + 1) * 32 + d4];
            acc0 += g0.x * wv.x; acc0 += g0.y * wv.y;
            acc0 += g0.z * wv.z; acc0 += g0.w * wv.w;
            acc1 += g1.x * wv.x; acc1 += g1.y * wv.y;
            acc1 += g1.z * wv.z; acc1 += g1.w * wv.w;
        }
    }

    out[(size_t)(b0 + g * 2)     * D + o] = acc0;
    out[(size_t)(b0 + g * 2 + 1) * D + o] = acc1;
}

// ---------------------------------------------------------------------------
extern "C" void kernel_launch(void* const* d_in, const int* in_sizes, int n_in,
                              void* d_out, int out_size)
{
    const float* x      = (const float*)d_in[0];
    const void*  batch  = d_in[1];
    const float* ps_raw = (const float*)d_in[2];
    const float* qs_raw = (const float*)d_in[3];
    const float* W      = (const float*)d_in[4];
    const float* bias   = (const float*)d_in[5];
    float*       out    = (float*)d_out;

    const int N = in_sizes[0] / D;    // node count from x (dtype-proof)
    const int B = out_size / D;       // 1024

    void *sum_ptr = nullptr, *cnt_ptr = nullptr;
    cudaGetSymbolAddress(&sum_ptr, g_sum);
    cudaGetSymbolAddress(&cnt_ptr, g_cnt);
    cudaMemsetAsync(sum_ptr, 0, (size_t)B * D * sizeof(float));
    cudaMemsetAsync(cnt_ptr, 0, (size_t)B * sizeof(int));

    const int grid1 = (N + CHUNK - 1) / CHUNK;
    k1_pool<<<grid1, 256>>>(x, batch, ps_raw, N);
    k2_gemm<<<B / 4, 256>>>(W, bias, ps_raw, qs_raw, out);
}

// round 3
// speedup vs baseline: 1.4760x; 1.2362x over previous
#include <cuda_runtime.h>
#include <math.h>

#define D      128
#define BMAX   1024
#define CHUNK  512

// Scratch (allocation-free rule: __device__ globals)
__device__ float g_sum[BMAX * D];
__device__ int   g_cnt[BMAX];

// softplus with the reference's Threshold(-50, 50) folding
__device__ __forceinline__ float softplus_thresh(float v) {
    float sp = fmaxf(v, 0.0f) + log1pf(expf(-fabsf(v)));
    return sp < 50.0f ? sp : -50.0f;
}

// ---------------------------------------------------------------------------
// Kernel 1: per-segment sum of (|x|+eps)^p  (p = ps0 for d<64, ps1 for d>=64)
// plus node counts. batch sorted -> register runs + atomic flush on boundary.
// 256 threads = 32 feature-quads (tx) x 8 node lanes (ty).
// Unroll-4 with all 4 LDG.128 issued up front (MLP=4).
// ---------------------------------------------------------------------------
__global__ void __launch_bounds__(256)
k1_pool(const float* __restrict__ x, const void* __restrict__ batch,
        const float* __restrict__ ps_raw, int N)
{
    __shared__ int sseg[CHUNK];

    const int tid = threadIdx.x;
    const int tx  = tid & 31;   // feature quad: features [4*tx, 4*tx+3]
    const int ty  = tid >> 5;   // node lane 0..7

    const long long start = (long long)blockIdx.x * CHUNK;
    const int len = (int)min((long long)CHUNK, (long long)N - start);

    // detect int32 vs int64 batch dtype (uniform across grid):
    // u64 at even idx ~N/4: int64 buffer -> small value; int32 -> >= 2^32
    const unsigned long long* p64b = (const unsigned long long*)batch;
    size_t q = ((size_t)(N >> 2)) & ~(size_t)1;
    const bool is64 = (p64b[q] < (1ull << 20));

    if (is64) {
        const long long* bb = (const long long*)batch;
        for (int i = tid; i < len; i += 256) sseg[i] = (int)bb[start + i];
    } else {
        const int* bb = (const int*)batch;
        for (int i = tid; i < len; i += 256) sseg[i] = bb[start + i];
    }
    __syncthreads();

    const float p = softplus_thresh(ps_raw[tx >> 4]);

    const float4* __restrict__ x4 = (const float4*)x + (size_t)start * 32 + tx;

    float ax = 0.f, ay = 0.f, az = 0.f, aw = 0.f;
    int cur = -1;
    int cnt = 0;

#define ACC4(v)                                   \
    ax += __powf(fabsf((v).x) + 1e-6f, p);        \
    ay += __powf(fabsf((v).y) + 1e-6f, p);        \
    az += __powf(fabsf((v).z) + 1e-6f, p);        \
    aw += __powf(fabsf((v).w) + 1e-6f, p);

#define FLUSH()                                                   \
    if (cnt > 0) {                                                \
        float* s = &g_sum[cur * D + tx * 4];                      \
        atomicAdd(s + 0, ax); atomicAdd(s + 1, ay);               \
        atomicAdd(s + 2, az); atomicAdd(s + 3, aw);               \
        if (tx == 0) atomicAdd(&g_cnt[cur], cnt);                 \
        ax = ay = az = aw = 0.f; cnt = 0;                         \
    }

#define PROC(v, b)                                \
    if ((b) != cur) { FLUSH(); cur = (b); }       \
    ACC4(v); cnt++;

    int j = ty;
    for (; j + 24 < len; j += 32) {
        // all 4 loads first: MLP = 4
        float4 v0 = x4[(size_t)(j)      * 32];
        float4 v1 = x4[(size_t)(j + 8)  * 32];
        float4 v2 = x4[(size_t)(j + 16) * 32];
        float4 v3 = x4[(size_t)(j + 24) * 32];
        int b0 = sseg[j];
        int b3 = sseg[j + 24];
        if (b0 == cur && b3 == cur) {          // sorted: b0==b3 => all equal
            ACC4(v0); ACC4(v1); ACC4(v2); ACC4(v3);
            cnt += 4;
        } else {
            int b1 = sseg[j + 8];
            int b2 = sseg[j + 16];
            PROC(v0, b0); PROC(v1, b1); PROC(v2, b2); PROC(v3, b3);
        }
    }
    for (; j < len; j += 8) {                   // tail (last partial chunk)
        float4 v = x4[(size_t)j * 32];
        int b = sseg[j];
        PROC(v, b);
    }
    FLUSH();

#undef PROC
#undef FLUSH
#undef ACC4
}

// ---------------------------------------------------------------------------
// Kernel 2: gnp[b][d] = s[b][d]^(1/p_d) * n_b^(-qs0);  out = gnp @ W^T + bias
// 512 threads, 8 graphs/block, grid = 128 (single wave). o = tid&127 output
// col; g = tid>>7 in {0..3} -> rows {2g, 2g+1}. W staged per-64-K-half in
// smem (float4, stride-17 padding -> conflict-free LDS.128), shared by all
// 4 row-groups (staging amortized 2x vs R2).
// ---------------------------------------------------------------------------
__global__ void __launch_bounds__(512)
k2_gemm(const float* __restrict__ W, const float* __restrict__ bias,
        const float* __restrict__ ps_raw, const float* __restrict__ qs_raw,
        float* __restrict__ out)
{
    __shared__ float w[128 * 68];     // 34.8 KB
    __shared__ float gs[8 * 128];     // 4 KB

    const int tid = threadIdx.x;
    const int o   = tid & 127;
    const int g   = tid >> 7;         // 0..3 -> rows {2g, 2g+1}
    const int b0  = blockIdx.x * 8;

    const float qs0 = tanhf(qs_raw[0]);

    // gnp for 8 rows: 1024 entries, 2 per thread
    for (int idx = tid; idx < 1024; idx += 512) {
        int r = idx >> 7, d = idx & 127;
        float p = softplus_thresh(ps_raw[d >> 6]);
        float s = g_sum[(b0 + r) * D + d];
        float n = (float)g_cnt[b0 + r];
        gs[idx] = __powf(s, 1.0f / p) * __powf(n, -qs0);
    }

    float acc0 = bias[o], acc1 = acc0;    // rows 2g and 2g+1

    const float4* __restrict__ W4 = (const float4*)W;
    float4* w4 = (float4*)w;
    const float4* gs4 = (const float4*)gs;

    #pragma unroll
    for (int half = 0; half < 2; half++) {
        __syncthreads();   // also orders gs writes before first read
        // stage W[:, half*64 .. half*64+63]: 128 rows x 16 float4, 4/thread
        for (int idx = tid; idx < 128 * 16; idx += 512) {
            int o2 = idx >> 4, dk4 = idx & 15;
            w4[o2 * 17 + dk4] = W4[o2 * 32 + half * 16 + dk4];
        }
        __syncthreads();

        #pragma unroll
        for (int dk4 = 0; dk4 < 16; dk4++) {
            float4 wv = w4[o * 17 + dk4];           // conflict-free
            int d4 = half * 16 + dk4;
            float4 g0 = gs4[(g * 2)     * 32 + d4]; // warp-uniform broadcast
            float4 g1 = gs4[(g * 2 + 1) * 32 + d4];
            acc0 += g0.x * wv.x; acc0 += g0.y * wv.y;
            acc0 += g0.z * wv.z; acc0 += g0.w * wv.w;
            acc1 += g1.x * wv.x; acc1 += g1.y * wv.y;
            acc1 += g1.z * wv.z; acc1 += g1.w * wv.w;
        }
    }

    out[(size_t)(b0 + g * 2)     * D + o] = acc0;
    out[(size_t)(b0 + g * 2 + 1) * D + o] = acc1;
}

// ---------------------------------------------------------------------------
extern "C" void kernel_launch(void* const* d_in, const int* in_sizes, int n_in,
                              void* d_out, int out_size)
{
    const float* x      = (const float*)d_in[0];
    const void*  batch  = d_in[1];
    const float* ps_raw = (const float*)d_in[2];
    const float* qs_raw = (const float*)d_in[3];
    const float* W      = (const float*)d_in[4];
    const float* bias   = (const float*)d_in[5];
    float*       out    = (float*)d_out;

    const int N = in_sizes[0] / D;    // node count from x (dtype-proof)
    const int B = out_size / D;       // 1024

    void *sum_ptr = nullptr, *cnt_ptr = nullptr;
    cudaGetSymbolAddress(&sum_ptr, g_sum);
    cudaGetSymbolAddress(&cnt_ptr, g_cnt);
    cudaMemsetAsync(sum_ptr, 0, (size_t)B * D * sizeof(float));
    cudaMemsetAsync(cnt_ptr, 0, (size_t)B * sizeof(int));

    const int grid1 = (N + CHUNK - 1) / CHUNK;
    k1_pool<<<grid1, 256>>>(x, batch, ps_raw, N);
    k2_gemm<<<B / 8, 512>>>(W, bias, ps_raw, qs_raw, out);
}

// round 4
// speedup vs baseline: 1.7103x; 1.1587x over previous
#include <cuda_runtime.h>
#include <math.h>

#define D      128
#define BMAX   1024
#define CHUNK  512

// One scratch buffer: [0, BMAX*D) = per-segment feature sums,
// [BMAX*D, BMAX*D+BMAX) = per-segment node counts (as float; exact < 2^24).
__device__ float g_buf[BMAX * D + BMAX];

// softplus with the reference's Threshold(-50, 50) folding
__device__ __forceinline__ float softplus_thresh(float v) {
    float sp = fmaxf(v, 0.0f) + log1pf(expf(-fabsf(v)));
    return sp < 50.0f ? sp : -50.0f;
}

// ---------------------------------------------------------------------------
// Kernel 1: per-segment sum of (|x|+eps)^p  (p = ps0 for d<64, ps1 for d>=64)
// plus node counts. batch sorted -> register runs + atomic flush on boundary.
// 256 threads = 32 feature-quads (tx) x 8 node lanes (ty).
// Rolling software pipeline: next iteration's 4 LDG.128 issued before the
// current iteration's pow chain -> loads always outstanding.
// ---------------------------------------------------------------------------
__global__ void __launch_bounds__(256)
k1_pool(const float* __restrict__ x, const void* __restrict__ batch,
        const float* __restrict__ ps_raw, int N)
{
    __shared__ int sseg[CHUNK];

    const int tid = threadIdx.x;
    const int tx  = tid & 31;   // feature quad: features [4*tx, 4*tx+3]
    const int ty  = tid >> 5;   // node lane 0..7

    const long long start = (long long)blockIdx.x * CHUNK;
    const int len = (int)min((long long)CHUNK, (long long)N - start);

    // detect int32 vs int64 batch dtype (uniform across grid):
    // u64 at even idx ~N/4: int64 buffer -> small value; int32 -> >= 2^32
    const unsigned long long* p64b = (const unsigned long long*)batch;
    size_t q = ((size_t)(N >> 2)) & ~(size_t)1;
    const bool is64 = (p64b[q] < (1ull << 20));

    if (is64) {
        const long long* bb = (const long long*)batch;
        for (int i = tid; i < len; i += 256) sseg[i] = (int)bb[start + i];
    } else {
        const int* bb = (const int*)batch;
        for (int i = tid; i < len; i += 256) sseg[i] = bb[start + i];
    }
    __syncthreads();

    const float p = softplus_thresh(ps_raw[tx >> 4]);

    const float4* __restrict__ x4 = (const float4*)x + (size_t)start * 32 + tx;
    float* __restrict__ cntf = g_buf + BMAX * D;

    float ax = 0.f, ay = 0.f, az = 0.f, aw = 0.f;
    int cur = -1;
    int cnt = 0;

#define ACC4(v)                                   \
    ax += __powf(fabsf((v).x) + 1e-6f, p);        \
    ay += __powf(fabsf((v).y) + 1e-6f, p);        \
    az += __powf(fabsf((v).z) + 1e-6f, p);        \
    aw += __powf(fabsf((v).w) + 1e-6f, p);

#define FLUSH()                                                   \
    if (cnt > 0) {                                                \
        float* s = &g_buf[cur * D + tx * 4];                      \
        atomicAdd(s + 0, ax); atomicAdd(s + 1, ay);               \
        atomicAdd(s + 2, az); atomicAdd(s + 3, aw);               \
        if (tx == 0) atomicAdd(&cntf[cur], (float)cnt);           \
        ax = ay = az = aw = 0.f; cnt = 0;                         \
    }

#define PROC(v, b)                                \
    if ((b) != cur) { FLUSH(); cur = (b); }       \
    ACC4(v); cnt++;

    int j = ty;
    bool have = (j + 24 < len);
    float4 v0, v1, v2, v3;
    if (have) {
        v0 = x4[(size_t)(j)      * 32];
        v1 = x4[(size_t)(j + 8)  * 32];
        v2 = x4[(size_t)(j + 16) * 32];
        v3 = x4[(size_t)(j + 24) * 32];
    }
    while (have) {
        const int jn = j + 32;
        const bool haven = (jn + 24 < len);
        float4 n0, n1, n2, n3;
        if (haven) {                     // prefetch next iteration (MLP ~8)
            n0 = x4[(size_t)(jn)      * 32];
            n1 = x4[(size_t)(jn + 8)  * 32];
            n2 = x4[(size_t)(jn + 16) * 32];
            n3 = x4[(size_t)(jn + 24) * 32];
        }
        int b0 = sseg[j];
        int b3 = sseg[j + 24];
        if (b0 == cur && b3 == cur) {    // sorted: b0==b3 => all 4 equal
            ACC4(v0); ACC4(v1); ACC4(v2); ACC4(v3);
            cnt += 4;
        } else {
            int b1 = sseg[j + 8];
            int b2 = sseg[j + 16];
            PROC(v0, b0); PROC(v1, b1); PROC(v2, b2); PROC(v3, b3);
        }
        v0 = n0; v1 = n1; v2 = n2; v3 = n3;
        j = jn; have = haven;
    }
    for (; j < len; j += 8) {            // tail (< 4 remaining per lane)
        float4 v = x4[(size_t)j * 32];
        int b = sseg[j];
        PROC(v, b);
    }
    FLUSH();

#undef PROC
#undef FLUSH
#undef ACC4
}

// ---------------------------------------------------------------------------
// Kernel 2: gnp[b][d] = s[b][d]^(1/p_d) * n_b^(-qs0);  out = gnp @ W^T + bias
// 256 blocks x 256 threads, 4 graph rows/block. NO smem staging of W:
// thread (g = tid>>7, o = tid&127) reads W row o directly via LDG (the two
// g-halves share rows -> L1 hits; 64KB unique W per block, 16MB L2 total).
// gs kept in smem (broadcast LDS.128). One __syncthreads total.
// ---------------------------------------------------------------------------
__global__ void __launch_bounds__(256)
k2_gemm(const float* __restrict__ W, const float* __restrict__ bias,
        const float* __restrict__ ps_raw, const float* __restrict__ qs_raw,
        float* __restrict__ out)
{
    __shared__ float gs[4 * 128];

    const int tid = threadIdx.x;
    const int o   = tid & 127;
    const int g   = tid >> 7;         // 0 or 1 -> rows {0,1} / {2,3}
    const int b0  = blockIdx.x * 4;

    const float qs0 = tanhf(qs_raw[0]);
    const float* __restrict__ cntf = g_buf + BMAX * D;

    // gnp for 4 rows: 512 entries, 2 per thread
    for (int idx = tid; idx < 512; idx += 256) {
        int r = idx >> 7, d = idx & 127;
        float p = softplus_thresh(ps_raw[d >> 6]);
        float s = g_buf[(b0 + r) * D + d];
        float n = cntf[b0 + r];
        gs[idx] = __powf(s, 1.0f / p) * __powf(n, -qs0);
    }
    __syncthreads();

    float acc0 = bias[o], acc1 = acc0;    // rows 2g and 2g+1

    const float4* __restrict__ W4  = (const float4*)W + o * 32;
    const float4* __restrict__ gs0 = (const float4*)gs + (g * 2) * 32;
    const float4* __restrict__ gs1 = (const float4*)gs + (g * 2 + 1) * 32;

    #pragma unroll 8
    for (int dk4 = 0; dk4 < 32; dk4++) {
        float4 wv = W4[dk4];              // LDG, L1/L2 resident
        float4 g0 = gs0[dk4];             // warp-uniform broadcast LDS
        float4 g1 = gs1[dk4];
        acc0 += g0.x * wv.x; acc0 += g0.y * wv.y;
        acc0 += g0.z * wv.z; acc0 += g0.w * wv.w;
        acc1 += g1.x * wv.x; acc1 += g1.y * wv.y;
        acc1 += g1.z * wv.z; acc1 += g1.w * wv.w;
    }

    out[(size_t)(b0 + g * 2)     * D + o] = acc0;
    out[(size_t)(b0 + g * 2 + 1) * D + o] = acc1;
}

// ---------------------------------------------------------------------------
extern "C" void kernel_launch(void* const* d_in, const int* in_sizes, int n_in,
                              void* d_out, int out_size)
{
    const float* x      = (const float*)d_in[0];
    const void*  batch  = d_in[1];
    const float* ps_raw = (const float*)d_in[2];
    const float* qs_raw = (const float*)d_in[3];
    const float* W      = (const float*)d_in[4];
    const float* bias   = (const float*)d_in[5];
    float*       out    = (float*)d_out;

    const int N = in_sizes[0] / D;    // node count from x (dtype-proof)
    const int B = out_size / D;       // 1024

    void* buf_ptr = nullptr;
    cudaGetSymbolAddress(&buf_ptr, g_buf);
    cudaMemsetAsync(buf_ptr, 0, (size_t)(BMAX * D + BMAX) * sizeof(float));

    const int grid1 = (N + CHUNK - 1) / CHUNK;
    k1_pool<<<grid1, 256>>>(x, batch, ps_raw, N);
    k2_gemm<<<B / 4, 256>>>(W, bias, ps_raw, qs_raw, out);
}

// round 5
// speedup vs baseline: 1.9059x; 1.1144x over previous
#include <cuda_runtime.h>
#include <math.h>

#define D      128
#define BMAX   1024
#define CHUNK  512

// Scratch: [0, BMAX*D) per-segment sums; [BMAX*D, +BMAX) counts (float).
// .bss => zero at module load. k2 re-zeroes everything it consumed, so the
// buffer is zero again before every subsequent kernel_launch replay.
__device__ float g_buf[BMAX * D + BMAX];

// softplus with the reference's Threshold(-50, 50) folding
__device__ __forceinline__ float softplus_thresh(float v) {
    float sp = fmaxf(v, 0.0f) + log1pf(expf(-fabsf(v)));
    return sp < 50.0f ? sp : -50.0f;
}

// ---------------------------------------------------------------------------
// Kernel 1: per-segment sum of (|x|+eps)^p  (p = ps0 for d<64, ps1 for d>=64)
// plus node counts. batch sorted -> register runs + atomic flush on boundary.
// 256 threads = 32 feature-quads (tx) x 8 node lanes (ty). Rolling software
// pipeline: next iteration's 4 LDG.128 issued before current pow chain.
// ---------------------------------------------------------------------------
__global__ void __launch_bounds__(256)
k1_pool(const float* __restrict__ x, const void* __restrict__ batch,
        const float* __restrict__ ps_raw, int N)
{
    __shared__ int sseg[CHUNK];

    const int tid = threadIdx.x;
    const int tx  = tid & 31;   // feature quad: features [4*tx, 4*tx+3]
    const int ty  = tid >> 5;   // node lane 0..7

    const long long start = (long long)blockIdx.x * CHUNK;
    const int len = (int)min((long long)CHUNK, (long long)N - start);

    // detect int32 vs int64 batch dtype (uniform across grid):
    // u64 at even idx ~N/4: int64 buffer -> small value; int32 -> >= 2^32
    const unsigned long long* p64b = (const unsigned long long*)batch;
    size_t q = ((size_t)(N >> 2)) & ~(size_t)1;
    const bool is64 = (p64b[q] < (1ull << 20));

    if (is64) {
        const long long* bb = (const long long*)batch;
        for (int i = tid; i < len; i += 256) sseg[i] = (int)bb[start + i];
    } else {
        const int* bb = (const int*)batch;
        for (int i = tid; i < len; i += 256) sseg[i] = bb[start + i];
    }
    __syncthreads();

    const float p = softplus_thresh(ps_raw[tx >> 4]);

    const float4* __restrict__ x4 = (const float4*)x + (size_t)start * 32 + tx;
    float* __restrict__ cntf = g_buf + BMAX * D;

    float ax = 0.f, ay = 0.f, az = 0.f, aw = 0.f;
    int cur = -1;
    int cnt = 0;

#define ACC4(v)                                   \
    ax += __powf(fabsf((v).x) + 1e-6f, p);        \
    ay += __powf(fabsf((v).y) + 1e-6f, p);        \
    az += __powf(fabsf((v).z) + 1e-6f, p);        \
    aw += __powf(fabsf((v).w) + 1e-6f, p);

#define FLUSH()                                                   \
    if (cnt > 0) {                                                \
        float* s = &g_buf[cur * D + tx * 4];                      \
        atomicAdd(s + 0, ax); atomicAdd(s + 1, ay);               \
        atomicAdd(s + 2, az); atomicAdd(s + 3, aw);               \
        if (tx == 0) atomicAdd(&cntf[cur], (float)cnt);           \
        ax = ay = az = aw = 0.f; cnt = 0;                         \
    }

#define PROC(v, b)                                \
    if ((b) != cur) { FLUSH(); cur = (b); }       \
    ACC4(v); cnt++;

    int j = ty;
    bool have = (j + 24 < len);
    float4 v0, v1, v2, v3;
    if (have) {
        v0 = x4[(size_t)(j)      * 32];
        v1 = x4[(size_t)(j + 8)  * 32];
        v2 = x4[(size_t)(j + 16) * 32];
        v3 = x4[(size_t)(j + 24) * 32];
    }
    while (have) {
        const int jn = j + 32;
        const bool haven = (jn + 24 < len);
        float4 n0, n1, n2, n3;
        if (haven) {                     // prefetch next iteration (MLP ~8)
            n0 = x4[(size_t)(jn)      * 32];
            n1 = x4[(size_t)(jn + 8)  * 32];
            n2 = x4[(size_t)(jn + 16) * 32];
            n3 = x4[(size_t)(jn + 24) * 32];
        }
        int b0 = sseg[j];
        int b3 = sseg[j + 24];
        if (b0 == cur && b3 == cur) {    // sorted: b0==b3 => all 4 equal
            ACC4(v0); ACC4(v1); ACC4(v2); ACC4(v3);
            cnt += 4;
        } else {
            int b1 = sseg[j + 8];
            int b2 = sseg[j + 16];
            PROC(v0, b0); PROC(v1, b1); PROC(v2, b2); PROC(v3, b3);
        }
        v0 = n0; v1 = n1; v2 = n2; v3 = n3;
        j = jn; have = haven;
    }
    for (; j < len; j += 8) {            // tail
        float4 v = x4[(size_t)j * 32];
        int b = sseg[j];
        PROC(v, b);
    }
    FLUSH();

#undef PROC
#undef FLUSH
#undef ACC4
}

// ---------------------------------------------------------------------------
// Kernel 2: gnp[b][d] = s[b][d]^(1/p_d) * n_b^(-qs0);  out = gnp @ W^T + bias
// 128 blocks x 256 threads, 8 graph rows/block. W staged per-64-K-half in
// smem (float4 rows, stride-17 pad -> conflict-free LDS.128). o = tid&127,
// g = tid>>7 -> rows {4g .. 4g+3} (4 accumulators/thread). After consuming
// g_buf this block re-zeroes its rows + counts (keeps scratch zero across
// graph replays; removes the memset launch).
// ---------------------------------------------------------------------------
__global__ void __launch_bounds__(256)
k2_gemm(const float* __restrict__ W, const float* __restrict__ bias,
        const float* __restrict__ ps_raw, const float* __restrict__ qs_raw,
        float* __restrict__ out)
{
    __shared__ float w[128 * 68];     // 34.8 KB
    __shared__ float gs[8 * 128];     // 4 KB

    const int tid = threadIdx.x;
    const int o   = tid & 127;
    const int g   = tid >> 7;         // 0/1 -> rows {4g..4g+3}
    const int b0  = blockIdx.x * 8;

    const float qs0 = tanhf(qs_raw[0]);
    float* __restrict__ cntf = g_buf + BMAX * D;

    // gnp for 8 rows: 1024 entries, 4 per thread
    for (int idx = tid; idx < 1024; idx += 256) {
        int r = idx >> 7, d = idx & 127;
        float p = softplus_thresh(ps_raw[d >> 6]);
        float s = g_buf[(b0 + r) * D + d];
        float n = cntf[b0 + r];
        gs[idx] = __powf(s, 1.0f / p) * __powf(n, -qs0);
    }
    __syncthreads();   // all block reads of g_buf complete

    // re-zero this block's scratch rows + counts (block-exclusive)
    {
        float4* gb4 = (float4*)(g_buf + (size_t)b0 * D);
        const float4 z4 = make_float4(0.f, 0.f, 0.f, 0.f);
        for (int idx = tid; idx < 256; idx += 256) gb4[idx] = z4;
        if (tid < 8) cntf[b0 + tid] = 0.f;
    }

    float acc0 = bias[o], acc1 = acc0, acc2 = acc0, acc3 = acc0;

    const float4* __restrict__ W4 = (const float4*)W;
    float4* w4 = (float4*)w;
    const float4* gs4 = (const float4*)gs;

    #pragma unroll
    for (int half = 0; half < 2; half++) {
        if (half) __syncthreads();
        // stage W[:, half*64 .. +63]: 128 rows x 16 float4, 8 per thread
        for (int idx = tid; idx < 128 * 16; idx += 256) {
            int o2 = idx >> 4, dk4 = idx & 15;
            w4[o2 * 17 + dk4] = W4[o2 * 32 + half * 16 + dk4];
        }
        __syncthreads();

        #pragma unroll
        for (int dk4 = 0; dk4 < 16; dk4++) {
            float4 wv = w4[o * 17 + dk4];            // conflict-free LDS.128
            int d4 = half * 16 + dk4;
            float4 g0 = gs4[(g * 4 + 0) * 32 + d4];  // warp-uniform broadcast
            float4 g1 = gs4[(g * 4 + 1) * 32 + d4];
            float4 g2 = gs4[(g * 4 + 2) * 32 + d4];
            float4 g3 = gs4[(g * 4 + 3) * 32 + d4];
            acc0 += g0.x * wv.x; acc0 += g0.y * wv.y;
            acc0 += g0.z * wv.z; acc0 += g0.w * wv.w;
            acc1 += g1.x * wv.x; acc1 += g1.y * wv.y;
            acc1 += g1.z * wv.z; acc1 += g1.w * wv.w;
            acc2 += g2.x * wv.x; acc2 += g2.y * wv.y;
            acc2 += g2.z * wv.z; acc2 += g2.w * wv.w;
            acc3 += g3.x * wv.x; acc3 += g3.y * wv.y;
            acc3 += g3.z * wv.z; acc3 += g3.w * wv.w;
        }
    }

    out[(size_t)(b0 + g * 4 + 0) * D + o] = acc0;
    out[(size_t)(b0 + g * 4 + 1) * D + o] = acc1;
    out[(size_t)(b0 + g * 4 + 2) * D + o] = acc2;
    out[(size_t)(b0 + g * 4 + 3) * D + o] = acc3;
}

// ---------------------------------------------------------------------------
extern "C" void kernel_launch(void* const* d_in, const int* in_sizes, int n_in,
                              void* d_out, int out_size)
{
    const float* x      = (const float*)d_in[0];
    const void*  batch  = d_in[1];
    const float* ps_raw = (const float*)d_in[2];
    const float* qs_raw = (const float*)d_in[3];
    const float* W      = (const float*)d_in[4];
    const float* bias   = (const float*)d_in[5];
    float*       out    = (float*)d_out;

    const int N = in_sizes[0] / D;    // node count from x (dtype-proof)
    const int B = out_size / D;       // 1024

    const int grid1 = (N + CHUNK - 1) / CHUNK;
    k1_pool<<<grid1, 256>>>(x, batch, ps_raw, N);
    k2_gemm<<<B / 8, 256>>>(W, bias, ps_raw, qs_raw, out);
}